// round 1
// baseline (speedup 1.0000x reference)
#include <cuda_runtime.h>
#include <cuda_bf16.h>
#include <cstdint>

// Problem constants
#define BATCH 4
#define SEQ   2048
#define EMB   1024
#define NHEAD 16
#define HDIM  64
#define M_ROWS (BATCH * SEQ)      // 8192
#define QKV_N  (3 * EMB)          // 3072

// Scratch (device globals: no allocation allowed in kernel_launch)
__device__ float g_qkv[(size_t)M_ROWS * QKV_N];  // (B*T, 3C)
__device__ float g_y[(size_t)M_ROWS * EMB];      // (B*T, C) attention output

// ---------------------------------------------------------------------------
// SGEMM: C[M,N] = A[M,K] @ B[K,N] + bias[N]
// BM=128 BN=128 BK=16, 256 threads, 8x8 per-thread tile, float4 loads.
// All dims assumed divisible (M=8192, N in {3072,1024}, K=1024).
// ---------------------------------------------------------------------------
#define BM 128
#define BN 128
#define BK 16
#define TM 8
#define TN 8

__global__ __launch_bounds__(256) void sgemm_bias(
    const float* __restrict__ A, const float* __restrict__ B,
    const float* __restrict__ bias, float* __restrict__ C,
    int M, int N, int K)
{
    __shared__ __align__(16) float As[BK][BM];
    __shared__ __align__(16) float Bs[BK][BN];

    const int tid = threadIdx.x;
    const int bm = blockIdx.y;
    const int bn = blockIdx.x;
    const int tx = tid & 15;     // 0..15
    const int ty = tid >> 4;     // 0..15

    float acc[TM][TN];
    #pragma unroll
    for (int i = 0; i < TM; i++)
        #pragma unroll
        for (int j = 0; j < TN; j++) acc[i][j] = 0.f;

    const float* Ablk = A + (size_t)bm * BM * K;
    const float* Bblk = B + (size_t)bn * BN;

    const int arow = tid >> 2;          // 0..63
    const int acol = (tid & 3) * 4;     // 0,4,8,12
    const int brow = tid >> 5;          // 0..7
    const int bcol = (tid & 31) * 4;    // 0..124

    for (int k0 = 0; k0 < K; k0 += BK) {
        #pragma unroll
        for (int i = 0; i < 2; i++) {
            int r = arow + i * 64;
            float4 v = *(const float4*)(Ablk + (size_t)r * K + k0 + acol);
            As[acol + 0][r] = v.x;
            As[acol + 1][r] = v.y;
            As[acol + 2][r] = v.z;
            As[acol + 3][r] = v.w;
        }
        #pragma unroll
        for (int i = 0; i < 2; i++) {
            int r = brow + i * 8;
            float4 v = *(const float4*)(Bblk + (size_t)(k0 + r) * N + bcol);
            *(float4*)&Bs[r][bcol] = v;
        }
        __syncthreads();

        #pragma unroll
        for (int k = 0; k < BK; k++) {
            float ra[TM], rb[TN];
            float4 a0 = *(const float4*)&As[k][ty * TM];
            float4 a1 = *(const float4*)&As[k][ty * TM + 4];
            ra[0]=a0.x; ra[1]=a0.y; ra[2]=a0.z; ra[3]=a0.w;
            ra[4]=a1.x; ra[5]=a1.y; ra[6]=a1.z; ra[7]=a1.w;
            float4 b0 = *(const float4*)&Bs[k][tx * TN];
            float4 b1 = *(const float4*)&Bs[k][tx * TN + 4];
            rb[0]=b0.x; rb[1]=b0.y; rb[2]=b0.z; rb[3]=b0.w;
            rb[4]=b1.x; rb[5]=b1.y; rb[6]=b1.z; rb[7]=b1.w;
            #pragma unroll
            for (int i = 0; i < TM; i++)
                #pragma unroll
                for (int j = 0; j < TN; j++)
                    acc[i][j] += ra[i] * rb[j];
        }
        __syncthreads();
    }

    #pragma unroll
    for (int i = 0; i < TM; i++) {
        int r = bm * BM + ty * TM + i;
        #pragma unroll
        for (int j = 0; j < TN; j += 4) {
            int c = bn * BN + tx * TN + j;
            float4 v;
            v.x = acc[i][j + 0] + bias[c + 0];
            v.y = acc[i][j + 1] + bias[c + 1];
            v.z = acc[i][j + 2] + bias[c + 2];
            v.w = acc[i][j + 3] + bias[c + 3];
            *(float4*)(C + (size_t)r * N + c) = v;
        }
    }
}

// ---------------------------------------------------------------------------
// Flash-attention forward (causal), fp32.
// One thread == one query row. Block = 128 query rows of one (b, h).
// K/V tiles (32 x 64) staged in SMEM, broadcast reads; online softmax is
// fully thread-local (no cross-thread reductions).
// qkv layout: row (b*T+t) of 3C floats; Q at col h*64, K at C+h*64, V at 2C+h*64.
// Output written directly in (B, T, C) layout with col = h*64+d.
// ---------------------------------------------------------------------------
#define KTILE 32

__global__ __launch_bounds__(128) void flash_fwd(
    const float* __restrict__ qkv, float* __restrict__ Y)
{
    const int b  = blockIdx.z;
    const int h  = blockIdx.y;
    const int qt = blockIdx.x;
    const int tid = threadIdx.x;
    const int t = qt * 128 + tid;          // global query index (always < SEQ)

    const float NEG_INF = __int_as_float(0xff800000);
    const size_t row3C = (size_t)QKV_N;
    const float* base = qkv + (size_t)b * SEQ * row3C;

    // Q row into registers (64 floats)
    float4 q[16];
    {
        const float* qrow = base + (size_t)t * row3C + h * HDIM;
        #pragma unroll
        for (int i = 0; i < 16; i++) q[i] = *(const float4*)(qrow + i * 4);
    }

    float o[HDIM];
    #pragma unroll
    for (int d = 0; d < HDIM; d++) o[d] = 0.f;
    float m = NEG_INF, l = 0.f;

    __shared__ __align__(16) float Ks[KTILE][HDIM];
    __shared__ __align__(16) float Vs[KTILE][HDIM];

    const float scale = 0.125f;  // 1/sqrt(64)
    const int ntiles = qt * 4 + 4;   // covers k <= max query in this block

    for (int kt = 0; kt < ntiles; kt++) {
        const int k0 = kt * KTILE;

        // cooperative K/V tile load: 32 rows x 64 cols = 512 float4s each
        #pragma unroll
        for (int i = 0; i < 4; i++) {
            int idx = tid + i * 128;         // 0..511
            int r = idx >> 4;                // 0..31
            int c = (idx & 15) * 4;          // 0..60
            const float* krow = base + (size_t)(k0 + r) * row3C + EMB + h * HDIM + c;
            *(float4*)&Ks[r][c] = *(const float4*)krow;
            *(float4*)&Vs[r][c] = *(const float4*)(krow + EMB);
        }
        __syncthreads();

        // S = q . K^T for this tile
        float s[KTILE];
        float tmax = NEG_INF;
        #pragma unroll
        for (int j = 0; j < KTILE; j++) {
            float acc = 0.f;
            #pragma unroll
            for (int i = 0; i < 16; i++) {
                float4 kk = *(const float4*)&Ks[j][i * 4];
                acc += q[i].x * kk.x + q[i].y * kk.y + q[i].z * kk.z + q[i].w * kk.w;
            }
            s[j] = (k0 + j <= t) ? acc * scale : NEG_INF;
            tmax = fmaxf(tmax, s[j]);
        }

        // online softmax update (thread-local)
        float mnew = fmaxf(m, tmax);        // always finite: k=0 <= t for tile 0
        float corr = __expf(m - mnew);      // exp(-inf - finite) = 0 first time
        m = mnew;
        l *= corr;
        #pragma unroll
        for (int d = 0; d < HDIM; d++) o[d] *= corr;

        #pragma unroll
        for (int j = 0; j < KTILE; j++) {
            float p = __expf(s[j] - mnew);  // masked entries -> exp(-inf)=0
            l += p;
            #pragma unroll
            for (int i = 0; i < 16; i++) {
                float4 vv = *(const float4*)&Vs[j][i * 4];
                o[i * 4 + 0] += p * vv.x;
                o[i * 4 + 1] += p * vv.y;
                o[i * 4 + 2] += p * vv.z;
                o[i * 4 + 3] += p * vv.w;
            }
        }
        __syncthreads();
    }

    const float inv = 1.f / l;
    float* yrow = Y + ((size_t)(b * SEQ + t)) * EMB + h * HDIM;
    #pragma unroll
    for (int i = 0; i < 16; i++) {
        float4 v;
        v.x = o[i * 4 + 0] * inv;
        v.y = o[i * 4 + 1] * inv;
        v.z = o[i * 4 + 2] * inv;
        v.w = o[i * 4 + 3] * inv;
        *(float4*)(yrow + i * 4) = v;
    }
}

// ---------------------------------------------------------------------------
// kernel_launch
// ---------------------------------------------------------------------------
extern "C" void kernel_launch(void* const* d_in, const int* in_sizes, int n_in,
                              void* d_out, int out_size)
{
    const float* x      = (const float*)d_in[0];   // (B,T,C)
    const float* W_attn = (const float*)d_in[1];   // (C, 3C)
    const float* b_attn = (const float*)d_in[2];   // (3C)
    const float* W_proj = (const float*)d_in[3];   // (C, C)
    const float* b_proj = (const float*)d_in[4];   // (C)
    float* out = (float*)d_out;                    // (B,T,C)

    float* qkv = nullptr;
    float* y   = nullptr;
    cudaGetSymbolAddress((void**)&qkv, g_qkv);
    cudaGetSymbolAddress((void**)&y,   g_y);

    // 1) QKV projection: (8192,1024) @ (1024,3072) + b_attn
    {
        dim3 grid(QKV_N / BN, M_ROWS / BM);
        sgemm_bias<<<grid, 256>>>(x, W_attn, b_attn, qkv, M_ROWS, QKV_N, EMB);
    }

    // 2) causal flash attention -> y in (B,T,C)
    {
        dim3 grid(SEQ / 128, NHEAD, BATCH);
        flash_fwd<<<grid, 128>>>(qkv, y);
    }

    // 3) output projection: (8192,1024) @ (1024,1024) + b_proj
    {
        dim3 grid(EMB / BN, M_ROWS / BM);
        sgemm_bias<<<grid, 256>>>(y, W_proj, b_proj, out, M_ROWS, EMB, EMB);
    }
}

// round 4
// speedup vs baseline: 1.2858x; 1.2858x over previous
#include <cuda_runtime.h>
#include <cuda_bf16.h>
#include <cstdint>

// Problem constants
#define BATCH 4
#define SEQ   2048
#define EMB   1024
#define NHEAD 16
#define HDIM  64
#define M_ROWS (BATCH * SEQ)      // 8192
#define QKV_N  (3 * EMB)          // 3072

// Scratch (device globals: no allocation allowed)
__device__ float g_qkv[(size_t)M_ROWS * QKV_N];   // (B*T, 3C)
__device__ float g_y[(size_t)M_ROWS * EMB];       // (B*T, C)
__device__ float g_wt_attn[(size_t)QKV_N * EMB];  // W_attn^T (3072,1024)
__device__ float g_wt_proj[(size_t)EMB * EMB];    // W_proj^T (1024,1024)

// ===========================================================================
// mma.sync tf32 GEMM: C[M,N] = A[M,K] @ Bt[N,K]^T + bias[N]
// BM=128 BN=128 BK=16, 256 threads = 8 warps (4M x 2N), warp tile 32x64.
// tf32 conversion via cvt.rna at smem store (zero-mean rounding error).
// Smem row stride 20 floats -> conflict-free fragment loads, 16B-aligned STS.
// ===========================================================================
#define BM 128
#define BN 128
#define BKT 16
#define ASTR 20   // smem row stride in floats

__device__ __forceinline__ uint32_t f2tf32(float f) {
    uint32_t r;
    asm("cvt.rna.tf32.f32 %0, %1;" : "=r"(r) : "f"(f));
    return r;
}

__device__ __forceinline__ void mma_tf32(float* c, const uint32_t* a, const uint32_t* b) {
    asm volatile(
        "mma.sync.aligned.m16n8k8.row.col.f32.tf32.tf32.f32 "
        "{%0,%1,%2,%3}, {%4,%5,%6,%7}, {%8,%9}, {%0,%1,%2,%3};"
        : "+f"(c[0]), "+f"(c[1]), "+f"(c[2]), "+f"(c[3])
        : "r"(a[0]), "r"(a[1]), "r"(a[2]), "r"(a[3]), "r"(b[0]), "r"(b[1]));
}

__global__ __launch_bounds__(256) void gemm_mma(
    const float* __restrict__ A, const float* __restrict__ Bt,
    const float* __restrict__ bias, float* __restrict__ C,
    int N, int K)
{
    __shared__ __align__(16) uint32_t As[2][BM * ASTR];  // [m][k]
    __shared__ __align__(16) uint32_t Bs[2][BN * ASTR];  // [n][k]

    const int tid  = threadIdx.x;
    const int warp = tid >> 5;
    const int lane = tid & 31;
    const int wm = warp >> 1;          // 0..3
    const int wn = warp & 1;           // 0..1
    const int g   = lane >> 2;         // 0..7
    const int tig = lane & 3;          // 0..3
    const int m0 = blockIdx.y * BM;
    const int n0 = blockIdx.x * BN;

    // loader mapping: each thread loads one 8-float segment of one row (A and B)
    const int lrow = tid >> 1;             // 0..127
    const int lkc  = (tid & 1) * 8;        // 0 or 8
    const float* Ap = A  + (size_t)(m0 + lrow) * K + lkc;
    const float* Bp = Bt + (size_t)(n0 + lrow) * K + lkc;

    float acc[2][8][4];
    #pragma unroll
    for (int i = 0; i < 2; i++)
        #pragma unroll
        for (int j = 0; j < 8; j++)
            #pragma unroll
            for (int r = 0; r < 4; r++) acc[i][j][r] = 0.f;

    const int niter = K / BKT;   // 64

    float4 ra0, ra1, rb0, rb1;

    // prologue: load tile 0
    ra0 = *(const float4*)(Ap + 0);
    ra1 = *(const float4*)(Ap + 4);
    rb0 = *(const float4*)(Bp + 0);
    rb1 = *(const float4*)(Bp + 4);
    {
        uint4 va = { f2tf32(ra0.x), f2tf32(ra0.y), f2tf32(ra0.z), f2tf32(ra0.w) };
        uint4 vb = { f2tf32(ra1.x), f2tf32(ra1.y), f2tf32(ra1.z), f2tf32(ra1.w) };
        *(uint4*)&As[0][lrow * ASTR + lkc + 0] = va;
        *(uint4*)&As[0][lrow * ASTR + lkc + 4] = vb;
        uint4 vc = { f2tf32(rb0.x), f2tf32(rb0.y), f2tf32(rb0.z), f2tf32(rb0.w) };
        uint4 vd = { f2tf32(rb1.x), f2tf32(rb1.y), f2tf32(rb1.z), f2tf32(rb1.w) };
        *(uint4*)&Bs[0][lrow * ASTR + lkc + 0] = vc;
        *(uint4*)&Bs[0][lrow * ASTR + lkc + 4] = vd;
    }
    __syncthreads();

    for (int it = 0; it < niter; it++) {
        const int cur = it & 1;
        const int nxt = cur ^ 1;

        // prefetch next tile into registers
        if (it + 1 < niter) {
            const int k0 = (it + 1) * BKT;
            ra0 = *(const float4*)(Ap + k0 + 0);
            ra1 = *(const float4*)(Ap + k0 + 4);
            rb0 = *(const float4*)(Bp + k0 + 0);
            rb1 = *(const float4*)(Bp + k0 + 4);
        }

        // compute: 2 k-steps of 8
        #pragma unroll
        for (int ks = 0; ks < 2; ks++) {
            const int kb = ks * 8;
            uint32_t af[2][4], bf[8][2];
            #pragma unroll
            for (int mf = 0; mf < 2; mf++) {
                const int base = (wm * 32 + mf * 16 + g) * ASTR + kb + tig;
                af[mf][0] = As[cur][base];
                af[mf][1] = As[cur][base + 8 * ASTR];
                af[mf][2] = As[cur][base + 4];
                af[mf][3] = As[cur][base + 8 * ASTR + 4];
            }
            #pragma unroll
            for (int nf = 0; nf < 8; nf++) {
                const int base = (wn * 64 + nf * 8 + g) * ASTR + kb + tig;
                bf[nf][0] = Bs[cur][base];
                bf[nf][1] = Bs[cur][base + 4];
            }
            #pragma unroll
            for (int mf = 0; mf < 2; mf++)
                #pragma unroll
                for (int nf = 0; nf < 8; nf++)
                    mma_tf32(acc[mf][nf], af[mf], bf[nf]);
        }

        // store prefetched tile into the other stage
        if (it + 1 < niter) {
            uint4 va = { f2tf32(ra0.x), f2tf32(ra0.y), f2tf32(ra0.z), f2tf32(ra0.w) };
            uint4 vb = { f2tf32(ra1.x), f2tf32(ra1.y), f2tf32(ra1.z), f2tf32(ra1.w) };
            *(uint4*)&As[nxt][lrow * ASTR + lkc + 0] = va;
            *(uint4*)&As[nxt][lrow * ASTR + lkc + 4] = vb;
            uint4 vc = { f2tf32(rb0.x), f2tf32(rb0.y), f2tf32(rb0.z), f2tf32(rb0.w) };
            uint4 vd = { f2tf32(rb1.x), f2tf32(rb1.y), f2tf32(rb1.z), f2tf32(rb1.w) };
            *(uint4*)&Bs[nxt][lrow * ASTR + lkc + 0] = vc;
            *(uint4*)&Bs[nxt][lrow * ASTR + lkc + 4] = vd;
        }
        __syncthreads();
    }

    // epilogue: acc + bias -> C
    #pragma unroll
    for (int mf = 0; mf < 2; mf++) {
        const int row = m0 + wm * 32 + mf * 16 + g;
        #pragma unroll
        for (int nf = 0; nf < 8; nf++) {
            const int col = n0 + wn * 64 + nf * 8 + tig * 2;
            const float b0 = __ldg(bias + col);
            const float b1 = __ldg(bias + col + 1);
            float2 v0 = { acc[mf][nf][0] + b0, acc[mf][nf][1] + b1 };
            float2 v1 = { acc[mf][nf][2] + b0, acc[mf][nf][3] + b1 };
            *(float2*)(C + (size_t)row * N + col)       = v0;
            *(float2*)(C + (size_t)(row + 8) * N + col) = v1;
        }
    }
}

// ===========================================================================
// transpose: out[c*R + r] = in[r*C + c]   (in: R x C)
// ===========================================================================
__global__ __launch_bounds__(256) void transpose_k(
    const float* __restrict__ in, float* __restrict__ out, int R, int C)
{
    __shared__ float t[32][33];
    const int bx = blockIdx.x * 32;
    const int by = blockIdx.y * 32;
    #pragma unroll
    for (int j = 0; j < 32; j += 8) {
        int r = by + threadIdx.y + j;
        t[threadIdx.y + j][threadIdx.x] = in[(size_t)r * C + bx + threadIdx.x];
    }
    __syncthreads();
    #pragma unroll
    for (int j = 0; j < 32; j += 8) {
        int c = bx + threadIdx.y + j;
        out[(size_t)c * R + by + threadIdx.x] = t[threadIdx.x][threadIdx.y + j];
    }
}

// ===========================================================================
// Flash-attention forward (causal), fp32 — unchanged (known good)
// ===========================================================================
#define KTILE 32

__global__ __launch_bounds__(128) void flash_fwd(
    const float* __restrict__ qkv, float* __restrict__ Y)
{
    const int b  = blockIdx.z;
    const int h  = blockIdx.y;
    const int qt = blockIdx.x;
    const int tid = threadIdx.x;
    const int t = qt * 128 + tid;

    const float NEG_INF = __int_as_float(0xff800000);
    const size_t row3C = (size_t)QKV_N;
    const float* base = qkv + (size_t)b * SEQ * row3C;

    float4 q[16];
    {
        const float* qrow = base + (size_t)t * row3C + h * HDIM;
        #pragma unroll
        for (int i = 0; i < 16; i++) q[i] = *(const float4*)(qrow + i * 4);
    }

    float o[HDIM];
    #pragma unroll
    for (int d = 0; d < HDIM; d++) o[d] = 0.f;
    float m = NEG_INF, l = 0.f;

    __shared__ __align__(16) float Ks[KTILE][HDIM];
    __shared__ __align__(16) float Vs[KTILE][HDIM];

    const float scale = 0.125f;
    const int ntiles = qt * 4 + 4;

    for (int kt = 0; kt < ntiles; kt++) {
        const int k0 = kt * KTILE;
        #pragma unroll
        for (int i = 0; i < 4; i++) {
            int idx = tid + i * 128;
            int r = idx >> 4;
            int c = (idx & 15) * 4;
            const float* krow = base + (size_t)(k0 + r) * row3C + EMB + h * HDIM + c;
            *(float4*)&Ks[r][c] = *(const float4*)krow;
            *(float4*)&Vs[r][c] = *(const float4*)(krow + EMB);
        }
        __syncthreads();

        float s[KTILE];
        float tmax = NEG_INF;
        #pragma unroll
        for (int j = 0; j < KTILE; j++) {
            float a = 0.f;
            #pragma unroll
            for (int i = 0; i < 16; i++) {
                float4 kk = *(const float4*)&Ks[j][i * 4];
                a += q[i].x * kk.x + q[i].y * kk.y + q[i].z * kk.z + q[i].w * kk.w;
            }
            s[j] = (k0 + j <= t) ? a * scale : NEG_INF;
            tmax = fmaxf(tmax, s[j]);
        }

        float mnew = fmaxf(m, tmax);
        float corr = __expf(m - mnew);
        m = mnew;
        l *= corr;
        #pragma unroll
        for (int d = 0; d < HDIM; d++) o[d] *= corr;

        #pragma unroll
        for (int j = 0; j < KTILE; j++) {
            float p = __expf(s[j] - mnew);
            l += p;
            #pragma unroll
            for (int i = 0; i < 16; i++) {
                float4 vv = *(const float4*)&Vs[j][i * 4];
                o[i * 4 + 0] += p * vv.x;
                o[i * 4 + 1] += p * vv.y;
                o[i * 4 + 2] += p * vv.z;
                o[i * 4 + 3] += p * vv.w;
            }
        }
        __syncthreads();
    }

    const float inv = 1.f / l;
    float* yrow = Y + ((size_t)(b * SEQ + t)) * EMB + h * HDIM;
    #pragma unroll
    for (int i = 0; i < 16; i++) {
        float4 v;
        v.x = o[i * 4 + 0] * inv;
        v.y = o[i * 4 + 1] * inv;
        v.z = o[i * 4 + 2] * inv;
        v.w = o[i * 4 + 3] * inv;
        *(float4*)(yrow + i * 4) = v;
    }
}

// ===========================================================================
// kernel_launch
// ===========================================================================
extern "C" void kernel_launch(void* const* d_in, const int* in_sizes, int n_in,
                              void* d_out, int out_size)
{
    const float* x      = (const float*)d_in[0];
    const float* W_attn = (const float*)d_in[1];
    const float* b_attn = (const float*)d_in[2];
    const float* W_proj = (const float*)d_in[3];
    const float* b_proj = (const float*)d_in[4];
    float* out = (float*)d_out;

    float *qkv, *y, *wt_attn, *wt_proj;
    cudaGetSymbolAddress((void**)&qkv, g_qkv);
    cudaGetSymbolAddress((void**)&y, g_y);
    cudaGetSymbolAddress((void**)&wt_attn, g_wt_attn);
    cudaGetSymbolAddress((void**)&wt_proj, g_wt_proj);

    // 0) transpose weights to K-major (N, K)
    {
        dim3 b(32, 8);
        transpose_k<<<dim3(QKV_N / 32, EMB / 32), b>>>(W_attn, wt_attn, EMB, QKV_N);
        transpose_k<<<dim3(EMB / 32, EMB / 32), b>>>(W_proj, wt_proj, EMB, EMB);
    }

    // 1) QKV projection (mma.sync tf32)
    {
        dim3 grid(QKV_N / BN, M_ROWS / BM);   // 24 x 64
        gemm_mma<<<grid, 256>>>(x, wt_attn, b_attn, qkv, QKV_N, EMB);
    }

    // 2) causal flash attention
    {
        dim3 grid(SEQ / 128, NHEAD, BATCH);
        flash_fwd<<<grid, 128>>>(qkv, y);
    }

    // 3) output projection (mma.sync tf32)
    {
        dim3 grid(EMB / BN, M_ROWS / BM);     // 8 x 64
        gemm_mma<<<grid, 256>>>(y, wt_proj, b_proj, out, EMB, EMB);
    }
}

// round 5
// speedup vs baseline: 2.9407x; 2.2871x over previous
#include <cuda_runtime.h>
#include <cuda_bf16.h>
#include <cstdint>

// Problem constants
#define BATCH 4
#define SEQ   2048
#define EMB   1024
#define NHEAD 16
#define HDIM  64
#define M_ROWS (BATCH * SEQ)      // 8192
#define QKV_N  (3 * EMB)          // 3072

// Scratch (device globals: no allocation allowed)
__device__ float g_qkv[(size_t)M_ROWS * QKV_N];   // (B*T, 3C)
__device__ float g_y[(size_t)M_ROWS * EMB];       // (B*T, C)
__device__ float g_wt_attn[(size_t)QKV_N * EMB];  // W_attn^T (3072,1024)
__device__ float g_wt_proj[(size_t)EMB * EMB];    // W_proj^T (1024,1024)

__device__ __forceinline__ uint32_t f2tf32(float f) {
    uint32_t r;
    asm("cvt.rna.tf32.f32 %0, %1;" : "=r"(r) : "f"(f));
    return r;
}

__device__ __forceinline__ void mma_tf32(float* c, const uint32_t* a, const uint32_t* b) {
    asm volatile(
        "mma.sync.aligned.m16n8k8.row.col.f32.tf32.tf32.f32 "
        "{%0,%1,%2,%3}, {%4,%5,%6,%7}, {%8,%9}, {%0,%1,%2,%3};"
        : "+f"(c[0]), "+f"(c[1]), "+f"(c[2]), "+f"(c[3])
        : "r"(a[0]), "r"(a[1]), "r"(a[2]), "r"(a[3]), "r"(b[0]), "r"(b[1]));
}

// ===========================================================================
// mma.sync tf32 GEMM: C[M,N] = A[M,K] @ Bt[N,K]^T + bias[N]  (unchanged, R4 WIN)
// ===========================================================================
#define BM 128
#define BN 128
#define BKT 16
#define ASTR 20

__global__ __launch_bounds__(256) void gemm_mma(
    const float* __restrict__ A, const float* __restrict__ Bt,
    const float* __restrict__ bias, float* __restrict__ C,
    int N, int K)
{
    __shared__ __align__(16) uint32_t As[2][BM * ASTR];
    __shared__ __align__(16) uint32_t Bs[2][BN * ASTR];

    const int tid  = threadIdx.x;
    const int warp = tid >> 5;
    const int lane = tid & 31;
    const int wm = warp >> 1;
    const int wn = warp & 1;
    const int g   = lane >> 2;
    const int tig = lane & 3;
    const int m0 = blockIdx.y * BM;
    const int n0 = blockIdx.x * BN;

    const int lrow = tid >> 1;
    const int lkc  = (tid & 1) * 8;
    const float* Ap = A  + (size_t)(m0 + lrow) * K + lkc;
    const float* Bp = Bt + (size_t)(n0 + lrow) * K + lkc;

    float acc[2][8][4];
    #pragma unroll
    for (int i = 0; i < 2; i++)
        #pragma unroll
        for (int j = 0; j < 8; j++)
            #pragma unroll
            for (int r = 0; r < 4; r++) acc[i][j][r] = 0.f;

    const int niter = K / BKT;
    float4 ra0, ra1, rb0, rb1;

    ra0 = *(const float4*)(Ap + 0);
    ra1 = *(const float4*)(Ap + 4);
    rb0 = *(const float4*)(Bp + 0);
    rb1 = *(const float4*)(Bp + 4);
    {
        uint4 va = { f2tf32(ra0.x), f2tf32(ra0.y), f2tf32(ra0.z), f2tf32(ra0.w) };
        uint4 vb = { f2tf32(ra1.x), f2tf32(ra1.y), f2tf32(ra1.z), f2tf32(ra1.w) };
        *(uint4*)&As[0][lrow * ASTR + lkc + 0] = va;
        *(uint4*)&As[0][lrow * ASTR + lkc + 4] = vb;
        uint4 vc = { f2tf32(rb0.x), f2tf32(rb0.y), f2tf32(rb0.z), f2tf32(rb0.w) };
        uint4 vd = { f2tf32(rb1.x), f2tf32(rb1.y), f2tf32(rb1.z), f2tf32(rb1.w) };
        *(uint4*)&Bs[0][lrow * ASTR + lkc + 0] = vc;
        *(uint4*)&Bs[0][lrow * ASTR + lkc + 4] = vd;
    }
    __syncthreads();

    for (int it = 0; it < niter; it++) {
        const int cur = it & 1;
        const int nxt = cur ^ 1;

        if (it + 1 < niter) {
            const int k0 = (it + 1) * BKT;
            ra0 = *(const float4*)(Ap + k0 + 0);
            ra1 = *(const float4*)(Ap + k0 + 4);
            rb0 = *(const float4*)(Bp + k0 + 0);
            rb1 = *(const float4*)(Bp + k0 + 4);
        }

        #pragma unroll
        for (int ks = 0; ks < 2; ks++) {
            const int kb = ks * 8;
            uint32_t af[2][4], bf[8][2];
            #pragma unroll
            for (int mf = 0; mf < 2; mf++) {
                const int base = (wm * 32 + mf * 16 + g) * ASTR + kb + tig;
                af[mf][0] = As[cur][base];
                af[mf][1] = As[cur][base + 8 * ASTR];
                af[mf][2] = As[cur][base + 4];
                af[mf][3] = As[cur][base + 8 * ASTR + 4];
            }
            #pragma unroll
            for (int nf = 0; nf < 8; nf++) {
                const int base = (wn * 64 + nf * 8 + g) * ASTR + kb + tig;
                bf[nf][0] = Bs[cur][base];
                bf[nf][1] = Bs[cur][base + 4];
            }
            #pragma unroll
            for (int mf = 0; mf < 2; mf++)
                #pragma unroll
                for (int nf = 0; nf < 8; nf++)
                    mma_tf32(acc[mf][nf], af[mf], bf[nf]);
        }

        if (it + 1 < niter) {
            uint4 va = { f2tf32(ra0.x), f2tf32(ra0.y), f2tf32(ra0.z), f2tf32(ra0.w) };
            uint4 vb = { f2tf32(ra1.x), f2tf32(ra1.y), f2tf32(ra1.z), f2tf32(ra1.w) };
            *(uint4*)&As[nxt][lrow * ASTR + lkc + 0] = va;
            *(uint4*)&As[nxt][lrow * ASTR + lkc + 4] = vb;
            uint4 vc = { f2tf32(rb0.x), f2tf32(rb0.y), f2tf32(rb0.z), f2tf32(rb0.w) };
            uint4 vd = { f2tf32(rb1.x), f2tf32(rb1.y), f2tf32(rb1.z), f2tf32(rb1.w) };
            *(uint4*)&Bs[nxt][lrow * ASTR + lkc + 0] = vc;
            *(uint4*)&Bs[nxt][lrow * ASTR + lkc + 4] = vd;
        }
        __syncthreads();
    }

    #pragma unroll
    for (int mf = 0; mf < 2; mf++) {
        const int row = m0 + wm * 32 + mf * 16 + g;
        #pragma unroll
        for (int nf = 0; nf < 8; nf++) {
            const int col = n0 + wn * 64 + nf * 8 + tig * 2;
            const float b0 = __ldg(bias + col);
            const float b1 = __ldg(bias + col + 1);
            float2 v0 = { acc[mf][nf][0] + b0, acc[mf][nf][1] + b1 };
            float2 v1 = { acc[mf][nf][2] + b0, acc[mf][nf][3] + b1 };
            *(float2*)(C + (size_t)row * N + col)       = v0;
            *(float2*)(C + (size_t)(row + 8) * N + col) = v1;
        }
    }
}

// ===========================================================================
// transpose: out[c*R + r] = in[r*C + c]
// ===========================================================================
__global__ __launch_bounds__(256) void transpose_k(
    const float* __restrict__ in, float* __restrict__ out, int R, int C)
{
    __shared__ float t[32][33];
    const int bx = blockIdx.x * 32;
    const int by = blockIdx.y * 32;
    #pragma unroll
    for (int j = 0; j < 32; j += 8) {
        int r = by + threadIdx.y + j;
        t[threadIdx.y + j][threadIdx.x] = in[(size_t)r * C + bx + threadIdx.x];
    }
    __syncthreads();
    #pragma unroll
    for (int j = 0; j < 32; j += 8) {
        int c = bx + threadIdx.y + j;
        out[(size_t)c * R + by + threadIdx.x] = t[threadIdx.x][threadIdx.y + j];
    }
}

// ===========================================================================
// Tensor-core flash attention (causal), mma.sync tf32.
// CTA: 64 query rows of one (b,h); 4 warps x 16 rows. Key tiles of 64.
// QK^T uses 3xTF32 (hi/lo split) for near-fp32 accuracy; PV uses rna tf32.
// Smem strides: K,P = 68 (frag rows indexed by g: need SR%32==4);
//               V   = 72 (frag rows indexed by tig: need SR%32==8).
// ===========================================================================
#define QT 64
#define KT 64
#define KSTR 68
#define VSTR 72
#define PSTR 68

// smem layout (floats)
#define S_KHI 0
#define S_KLO (S_KHI + KT * KSTR)          // 4352
#define S_V   (S_KLO + KT * KSTR)          // 8704
#define S_P   (S_V + KT * VSTR)            // 13312
#define FLASH_SMEM_FLOATS (S_P + 4 * 16 * PSTR)   // 17664
#define FLASH_SMEM_BYTES  (FLASH_SMEM_FLOATS * 4) // 70656

__global__ __launch_bounds__(128) void flash_mma(
    const float* __restrict__ qkv, float* __restrict__ Y)
{
    extern __shared__ __align__(16) float sm[];
    uint32_t* smu = (uint32_t*)sm;

    const int b  = blockIdx.z;
    const int h  = blockIdx.y;
    const int qt = gridDim.x - 1 - blockIdx.x;   // heavy blocks first
    const int qb = qt * QT;
    const int tid  = threadIdx.x;
    const int w    = tid >> 5;
    const int lane = tid & 31;
    const int g    = lane >> 2;
    const int tig  = lane & 3;

    const float* base = qkv + (size_t)b * SEQ * QKV_N;

    // ---- Q fragments (scaled by 1/8 exactly, split hi/lo) ----
    uint32_t qhi[8][4], qlo[8][4];
    {
        const float* qlorow = base + (size_t)(qb + w * 16 + g) * QKV_N + h * HDIM;
        const float* qhirow = qlorow + 8 * QKV_N;
        #pragma unroll
        for (int kk = 0; kk < 8; kk++) {
            float v0 = qlorow[kk * 8 + tig]     * 0.125f;
            float v1 = qhirow[kk * 8 + tig]     * 0.125f;
            float v2 = qlorow[kk * 8 + tig + 4] * 0.125f;
            float v3 = qhirow[kk * 8 + tig + 4] * 0.125f;
            float h0 = __uint_as_float(__float_as_uint(v0) & 0xffffe000u);
            float h1 = __uint_as_float(__float_as_uint(v1) & 0xffffe000u);
            float h2 = __uint_as_float(__float_as_uint(v2) & 0xffffe000u);
            float h3 = __uint_as_float(__float_as_uint(v3) & 0xffffe000u);
            qhi[kk][0] = __float_as_uint(h0);
            qhi[kk][1] = __float_as_uint(h1);
            qhi[kk][2] = __float_as_uint(h2);
            qhi[kk][3] = __float_as_uint(h3);
            qlo[kk][0] = f2tf32(v0 - h0);
            qlo[kk][1] = f2tf32(v1 - h1);
            qlo[kk][2] = f2tf32(v2 - h2);
            qlo[kk][3] = f2tf32(v3 - h3);
        }
    }

    float o[8][4];
    #pragma unroll
    for (int nt = 0; nt < 8; nt++)
        #pragma unroll
        for (int r = 0; r < 4; r++) o[nt][r] = 0.f;
    float m_lo = -1e30f, m_hi = -1e30f;
    float l_lo = 0.f,    l_hi = 0.f;

    uint32_t* Pw = smu + S_P + w * 16 * PSTR;

    for (int kt = 0; kt <= qt; kt++) {
        const int k0 = kt * KT;

        // ---- load K (hi/lo split) and V (rna tf32) tiles ----
        __syncthreads();   // previous iteration's reads complete
        #pragma unroll
        for (int i = 0; i < 8; i++) {
            int idx = i * 128 + tid;         // 0..1023
            int r = idx >> 4;                // 0..63
            int c = (idx & 15) * 4;
            const float* krow = base + (size_t)(k0 + r) * QKV_N + EMB + h * HDIM + c;
            float4 kv = *(const float4*)krow;
            float4 vv = *(const float4*)(krow + EMB);
            float kh, kl;
            uint32_t* KH = smu + S_KHI + r * KSTR + c;
            uint32_t* KL = smu + S_KLO + r * KSTR + c;
            kh = __uint_as_float(__float_as_uint(kv.x) & 0xffffe000u); KH[0] = __float_as_uint(kh); KL[0] = f2tf32(kv.x - kh);
            kh = __uint_as_float(__float_as_uint(kv.y) & 0xffffe000u); KH[1] = __float_as_uint(kh); KL[1] = f2tf32(kv.y - kh);
            kh = __uint_as_float(__float_as_uint(kv.z) & 0xffffe000u); KH[2] = __float_as_uint(kh); KL[2] = f2tf32(kv.z - kh);
            kh = __uint_as_float(__float_as_uint(kv.w) & 0xffffe000u); KH[3] = __float_as_uint(kh); KL[3] = f2tf32(kv.w - kh);
            uint32_t* VS = smu + S_V + r * VSTR + c;
            VS[0] = f2tf32(vv.x);
            VS[1] = f2tf32(vv.y);
            VS[2] = f2tf32(vv.z);
            VS[3] = f2tf32(vv.w);
            (void)kl;
        }
        __syncthreads();

        // ---- S = Q.K^T (3xTF32) ----
        float s[8][4];
        #pragma unroll
        for (int nt = 0; nt < 8; nt++)
            #pragma unroll
            for (int r = 0; r < 4; r++) s[nt][r] = 0.f;

        #pragma unroll
        for (int kk = 0; kk < 8; kk++) {
            #pragma unroll
            for (int nt = 0; nt < 8; nt++) {
                const int ra = nt * 8 + g;
                uint32_t bh[2], bl[2];
                bh[0] = smu[S_KHI + ra * KSTR + kk * 8 + tig];
                bh[1] = smu[S_KHI + ra * KSTR + kk * 8 + tig + 4];
                bl[0] = smu[S_KLO + ra * KSTR + kk * 8 + tig];
                bl[1] = smu[S_KLO + ra * KSTR + kk * 8 + tig + 4];
                mma_tf32(s[nt], qhi[kk], bh);
                mma_tf32(s[nt], qhi[kk], bl);
                mma_tf32(s[nt], qlo[kk], bh);
            }
        }

        // ---- causal mask (diagonal tile only) ----
        if (kt == qt) {
            const int rlo = w * 16 + g;
            const int rhi = rlo + 8;
            #pragma unroll
            for (int nt = 0; nt < 8; nt++) {
                const int c0 = nt * 8 + 2 * tig;
                if (c0     > rlo) s[nt][0] = -1e30f;
                if (c0 + 1 > rlo) s[nt][1] = -1e30f;
                if (c0     > rhi) s[nt][2] = -1e30f;
                if (c0 + 1 > rhi) s[nt][3] = -1e30f;
            }
        }

        // ---- online softmax ----
        float mx_lo = -1e30f, mx_hi = -1e30f;
        #pragma unroll
        for (int nt = 0; nt < 8; nt++) {
            mx_lo = fmaxf(mx_lo, fmaxf(s[nt][0], s[nt][1]));
            mx_hi = fmaxf(mx_hi, fmaxf(s[nt][2], s[nt][3]));
        }
        mx_lo = fmaxf(mx_lo, __shfl_xor_sync(0xffffffffu, mx_lo, 1));
        mx_lo = fmaxf(mx_lo, __shfl_xor_sync(0xffffffffu, mx_lo, 2));
        mx_hi = fmaxf(mx_hi, __shfl_xor_sync(0xffffffffu, mx_hi, 1));
        mx_hi = fmaxf(mx_hi, __shfl_xor_sync(0xffffffffu, mx_hi, 2));

        const float mn_lo = fmaxf(m_lo, mx_lo);
        const float mn_hi = fmaxf(m_hi, mx_hi);
        const float cr_lo = __expf(m_lo - mn_lo);
        const float cr_hi = __expf(m_hi - mn_hi);
        m_lo = mn_lo; m_hi = mn_hi;
        l_lo *= cr_lo; l_hi *= cr_hi;
        #pragma unroll
        for (int nt = 0; nt < 8; nt++) {
            o[nt][0] *= cr_lo;
            o[nt][1] *= cr_lo;
            o[nt][2] *= cr_hi;
            o[nt][3] *= cr_hi;
        }

        // ---- P = exp(s - m), accumulate l, stage P to smem ----
        #pragma unroll
        for (int nt = 0; nt < 8; nt++) {
            float p0 = __expf(s[nt][0] - mn_lo);
            float p1 = __expf(s[nt][1] - mn_lo);
            float p2 = __expf(s[nt][2] - mn_hi);
            float p3 = __expf(s[nt][3] - mn_hi);
            l_lo += p0 + p1;
            l_hi += p2 + p3;
            uint32_t* Plo = Pw + g * PSTR + nt * 8 + 2 * tig;
            uint32_t* Phi = Pw + (g + 8) * PSTR + nt * 8 + 2 * tig;
            Plo[0] = f2tf32(p0);
            Plo[1] = f2tf32(p1);
            Phi[0] = f2tf32(p2);
            Phi[1] = f2tf32(p3);
        }
        __syncwarp();

        // ---- O += P.V ----
        #pragma unroll
        for (int kk = 0; kk < 8; kk++) {
            uint32_t pa[4];
            pa[0] = Pw[g * PSTR + kk * 8 + tig];
            pa[1] = Pw[(g + 8) * PSTR + kk * 8 + tig];
            pa[2] = Pw[g * PSTR + kk * 8 + tig + 4];
            pa[3] = Pw[(g + 8) * PSTR + kk * 8 + tig + 4];
            #pragma unroll
            for (int nt = 0; nt < 8; nt++) {
                uint32_t vb[2];
                vb[0] = smu[S_V + (kk * 8 + tig) * VSTR + nt * 8 + g];
                vb[1] = smu[S_V + (kk * 8 + tig + 4) * VSTR + nt * 8 + g];
                mma_tf32(o[nt], pa, vb);
            }
        }
        __syncwarp();
    }

    // ---- finalize: full row sums, normalize, write ----
    l_lo += __shfl_xor_sync(0xffffffffu, l_lo, 1);
    l_lo += __shfl_xor_sync(0xffffffffu, l_lo, 2);
    l_hi += __shfl_xor_sync(0xffffffffu, l_hi, 1);
    l_hi += __shfl_xor_sync(0xffffffffu, l_hi, 2);
    const float inv_lo = 1.f / l_lo;
    const float inv_hi = 1.f / l_hi;

    const int row_lo = qb + w * 16 + g;
    float* ylo = Y + (size_t)(b * SEQ + row_lo) * EMB + h * HDIM;
    float* yhi = ylo + 8 * EMB;
    #pragma unroll
    for (int nt = 0; nt < 8; nt++) {
        const int col = nt * 8 + 2 * tig;
        float2 v0 = { o[nt][0] * inv_lo, o[nt][1] * inv_lo };
        float2 v1 = { o[nt][2] * inv_hi, o[nt][3] * inv_hi };
        *(float2*)(ylo + col) = v0;
        *(float2*)(yhi + col) = v1;
    }
}

// ===========================================================================
// kernel_launch
// ===========================================================================
extern "C" void kernel_launch(void* const* d_in, const int* in_sizes, int n_in,
                              void* d_out, int out_size)
{
    const float* x      = (const float*)d_in[0];
    const float* W_attn = (const float*)d_in[1];
    const float* b_attn = (const float*)d_in[2];
    const float* W_proj = (const float*)d_in[3];
    const float* b_proj = (const float*)d_in[4];
    float* out = (float*)d_out;

    float *qkv, *y, *wt_attn, *wt_proj;
    cudaGetSymbolAddress((void**)&qkv, g_qkv);
    cudaGetSymbolAddress((void**)&y, g_y);
    cudaGetSymbolAddress((void**)&wt_attn, g_wt_attn);
    cudaGetSymbolAddress((void**)&wt_proj, g_wt_proj);

    static bool attr_set = false;
    if (!attr_set) {
        cudaFuncSetAttribute(flash_mma, cudaFuncAttributeMaxDynamicSharedMemorySize,
                             FLASH_SMEM_BYTES);
        attr_set = true;
    }

    // 0) transpose weights to K-major (N, K)
    {
        dim3 bdim(32, 8);
        transpose_k<<<dim3(QKV_N / 32, EMB / 32), bdim>>>(W_attn, wt_attn, EMB, QKV_N);
        transpose_k<<<dim3(EMB / 32, EMB / 32), bdim>>>(W_proj, wt_proj, EMB, EMB);
    }

    // 1) QKV projection (mma.sync tf32)
    {
        dim3 grid(QKV_N / BN, M_ROWS / BM);
        gemm_mma<<<grid, 256>>>(x, wt_attn, b_attn, qkv, QKV_N, EMB);
    }

    // 2) causal flash attention (mma.sync tf32, 3xTF32 for QK)
    {
        dim3 grid(SEQ / QT, NHEAD, BATCH);
        flash_mma<<<grid, 128, FLASH_SMEM_BYTES>>>(qkv, y);
    }

    // 3) output projection (mma.sync tf32)
    {
        dim3 grid(EMB / BN, M_ROWS / BM);
        gemm_mma<<<grid, 256>>>(y, wt_proj, b_proj, out, EMB, EMB);
    }
}

// round 9
// speedup vs baseline: 3.3307x; 1.1326x over previous
#include <cuda_runtime.h>
#include <cuda_bf16.h>
#include <cstdint>

// Problem constants
#define BATCH 4
#define SEQ   2048
#define EMB   1024
#define NHEAD 16
#define HDIM  64
#define M_ROWS (BATCH * SEQ)      // 8192
#define QKV_N  (3 * EMB)          // 3072

// Scratch (device globals: no allocation allowed)
__device__ float g_qkv[(size_t)M_ROWS * QKV_N];   // (B*T, 3C)
__device__ float g_y[(size_t)M_ROWS * EMB];       // (B*T, C)
__device__ float g_wt_attn[(size_t)QKV_N * EMB];  // W_attn^T (3072,1024), tf32-rounded
__device__ float g_wt_proj[(size_t)EMB * EMB];    // W_proj^T (1024,1024), tf32-rounded

__device__ __forceinline__ uint32_t f2tf32(float f) {
    uint32_t r;
    asm("cvt.rna.tf32.f32 %0, %1;" : "=r"(r) : "f"(f));
    return r;
}

__device__ __forceinline__ void mma_tf32(float* c, const uint32_t* a, const uint32_t* b) {
    asm volatile(
        "mma.sync.aligned.m16n8k8.row.col.f32.tf32.tf32.f32 "
        "{%0,%1,%2,%3}, {%4,%5,%6,%7}, {%8,%9}, {%0,%1,%2,%3};"
        : "+f"(c[0]), "+f"(c[1]), "+f"(c[2]), "+f"(c[3])
        : "r"(a[0]), "r"(a[1]), "r"(a[2]), "r"(a[3]), "r"(b[0]), "r"(b[1]));
}

__device__ __forceinline__ void cpa16(void* dst_smem, const void* src) {
    uint32_t d = (uint32_t)__cvta_generic_to_shared(dst_smem);
    asm volatile("cp.async.cg.shared.global [%0], [%1], 16;" :: "r"(d), "l"(src) : "memory");
}
#define CP_COMMIT() asm volatile("cp.async.commit_group;" ::: "memory")
#define CP_WAIT2()  asm volatile("cp.async.wait_group 2;" ::: "memory")

// ===========================================================================
// mma.sync tf32 GEMM with 4-stage cp.async pipeline (DYNAMIC smem, 80KB).
// C[M,N] = A[M,K] @ Bt[N,K]^T + bias[N]
// BM=128 BN=128 BK=16, 256 threads = 8 warps (4M x 2N), warp tile 32x64.
// Bt is tf32-pre-rounded (transpose pass); A converted via cvt.rna at frag load.
// Smem row stride 20 floats -> conflict-free fragment loads, 16B-aligned cp.async.
// ===========================================================================
#define BM 128
#define BN 128
#define BKT 16
#define ASTR 20
#define NST 4

#define GEMM_AS_FLOATS (BM * ASTR)                       // 2560 per stage
#define GEMM_BS_FLOATS (BN * ASTR)                       // 2560 per stage
#define GEMM_SMEM_FLOATS (NST * (GEMM_AS_FLOATS + GEMM_BS_FLOATS))   // 20480
#define GEMM_SMEM_BYTES  (GEMM_SMEM_FLOATS * 4)          // 81920

__global__ __launch_bounds__(256, 2) void gemm_mma(
    const float* __restrict__ A, const float* __restrict__ Bt,
    const float* __restrict__ bias, float* __restrict__ C,
    int N, int K)
{
    extern __shared__ __align__(16) float gsm[];
    // layout: As[NST][2560] then Bs[NST][2560]
    float* Asm = gsm;
    float* Bsm = gsm + NST * GEMM_AS_FLOATS;

    const int tid  = threadIdx.x;
    const int warp = tid >> 5;
    const int lane = tid & 31;
    const int wm = warp >> 1;
    const int wn = warp & 1;
    const int g   = lane >> 2;
    const int tig = lane & 3;
    const int m0 = blockIdx.y * BM;
    const int n0 = blockIdx.x * BN;

    // loader mapping: 2 chunks (16B) per thread per operand per stage
    const int ch0 = tid * 2;
    const int lr0 = ch0 >> 2;            // row of chunk 0
    const int lk0 = (ch0 & 3) * 4;       // k-offset of chunk 0
    const int lr1 = (ch0 + 1) >> 2;
    const int lk1 = ((ch0 + 1) & 3) * 4;

    const float* Abase = A  + (size_t)m0 * K;
    const float* Bbase = Bt + (size_t)n0 * K;

    float acc[2][8][4];
    #pragma unroll
    for (int i = 0; i < 2; i++)
        #pragma unroll
        for (int j = 0; j < 8; j++)
            #pragma unroll
            for (int r = 0; r < 4; r++) acc[i][j][r] = 0.f;

    const int niter = K / BKT;   // 64

    // prologue: issue stages 0..2
    #pragma unroll
    for (int s = 0; s < NST - 1; s++) {
        const int k0 = s * BKT;
        cpa16(&Asm[s * GEMM_AS_FLOATS + lr0 * ASTR + lk0], Abase + (size_t)lr0 * K + k0 + lk0);
        cpa16(&Asm[s * GEMM_AS_FLOATS + lr1 * ASTR + lk1], Abase + (size_t)lr1 * K + k0 + lk1);
        cpa16(&Bsm[s * GEMM_BS_FLOATS + lr0 * ASTR + lk0], Bbase + (size_t)lr0 * K + k0 + lk0);
        cpa16(&Bsm[s * GEMM_BS_FLOATS + lr1 * ASTR + lk1], Bbase + (size_t)lr1 * K + k0 + lk1);
        CP_COMMIT();
    }

    for (int it = 0; it < niter; it++) {
        const int st = it & (NST - 1);
        const float* As = Asm + st * GEMM_AS_FLOATS;
        const float* Bs = Bsm + st * GEMM_BS_FLOATS;

        CP_WAIT2();
        __syncthreads();

        // issue stage it+3 (overwrites stage (it-1)&3, which all warps finished)
        const int pre = it + NST - 1;
        if (pre < niter) {
            const int ps = pre & (NST - 1);
            const int k0 = pre * BKT;
            cpa16(&Asm[ps * GEMM_AS_FLOATS + lr0 * ASTR + lk0], Abase + (size_t)lr0 * K + k0 + lk0);
            cpa16(&Asm[ps * GEMM_AS_FLOATS + lr1 * ASTR + lk1], Abase + (size_t)lr1 * K + k0 + lk1);
            cpa16(&Bsm[ps * GEMM_BS_FLOATS + lr0 * ASTR + lk0], Bbase + (size_t)lr0 * K + k0 + lk0);
            cpa16(&Bsm[ps * GEMM_BS_FLOATS + lr1 * ASTR + lk1], Bbase + (size_t)lr1 * K + k0 + lk1);
        }
        CP_COMMIT();

        // compute on stage st
        #pragma unroll
        for (int ks = 0; ks < 2; ks++) {
            const int kb = ks * 8;
            uint32_t af[2][4], bf[8][2];
            #pragma unroll
            for (int mf = 0; mf < 2; mf++) {
                const int base = (wm * 32 + mf * 16 + g) * ASTR + kb + tig;
                af[mf][0] = f2tf32(As[base]);
                af[mf][1] = f2tf32(As[base + 8 * ASTR]);
                af[mf][2] = f2tf32(As[base + 4]);
                af[mf][3] = f2tf32(As[base + 8 * ASTR + 4]);
            }
            #pragma unroll
            for (int nf = 0; nf < 8; nf++) {
                const int base = (wn * 64 + nf * 8 + g) * ASTR + kb + tig;
                bf[nf][0] = __float_as_uint(Bs[base]);      // pre-rounded tf32
                bf[nf][1] = __float_as_uint(Bs[base + 4]);
            }
            #pragma unroll
            for (int mf = 0; mf < 2; mf++)
                #pragma unroll
                for (int nf = 0; nf < 8; nf++)
                    mma_tf32(acc[mf][nf], af[mf], bf[nf]);
        }
    }

    // epilogue: acc + bias -> C
    #pragma unroll
    for (int mf = 0; mf < 2; mf++) {
        const int row = m0 + wm * 32 + mf * 16 + g;
        #pragma unroll
        for (int nf = 0; nf < 8; nf++) {
            const int col = n0 + wn * 64 + nf * 8 + tig * 2;
            const float b0 = __ldg(bias + col);
            const float b1 = __ldg(bias + col + 1);
            float2 v0 = { acc[mf][nf][0] + b0, acc[mf][nf][1] + b1 };
            float2 v1 = { acc[mf][nf][2] + b0, acc[mf][nf][3] + b1 };
            *(float2*)(C + (size_t)row * N + col)       = v0;
            *(float2*)(C + (size_t)(row + 8) * N + col) = v1;
        }
    }
}

// ===========================================================================
// transpose + tf32 round: out[c*R + r] = rna_tf32(in[r*C + c])
// ===========================================================================
__global__ __launch_bounds__(256) void transpose_k(
    const float* __restrict__ in, float* __restrict__ out, int R, int C)
{
    __shared__ float t[32][33];
    const int bx = blockIdx.x * 32;
    const int by = blockIdx.y * 32;
    #pragma unroll
    for (int j = 0; j < 32; j += 8) {
        int r = by + threadIdx.y + j;
        t[threadIdx.y + j][threadIdx.x] = in[(size_t)r * C + bx + threadIdx.x];
    }
    __syncthreads();
    #pragma unroll
    for (int j = 0; j < 32; j += 8) {
        int c = bx + threadIdx.y + j;
        out[(size_t)c * R + by + threadIdx.x] =
            __uint_as_float(f2tf32(t[threadIdx.x][threadIdx.y + j]));
    }
}

// ===========================================================================
// Tensor-core flash attention (causal), mma.sync tf32 — unchanged (R5 WIN).
// ===========================================================================
#define QT 64
#define KT 64
#define KSTR 68
#define VSTR 72
#define PSTR 68

#define S_KHI 0
#define S_KLO (S_KHI + KT * KSTR)
#define S_V   (S_KLO + KT * KSTR)
#define S_P   (S_V + KT * VSTR)
#define FLASH_SMEM_FLOATS (S_P + 4 * 16 * PSTR)
#define FLASH_SMEM_BYTES  (FLASH_SMEM_FLOATS * 4)

__global__ __launch_bounds__(128) void flash_mma(
    const float* __restrict__ qkv, float* __restrict__ Y)
{
    extern __shared__ __align__(16) float sm[];
    uint32_t* smu = (uint32_t*)sm;

    const int b  = blockIdx.z;
    const int h  = blockIdx.y;
    const int qt = gridDim.x - 1 - blockIdx.x;
    const int qb = qt * QT;
    const int tid  = threadIdx.x;
    const int w    = tid >> 5;
    const int lane = tid & 31;
    const int g    = lane >> 2;
    const int tig  = lane & 3;

    const float* base = qkv + (size_t)b * SEQ * QKV_N;

    uint32_t qhi[8][4], qlo[8][4];
    {
        const float* qlorow = base + (size_t)(qb + w * 16 + g) * QKV_N + h * HDIM;
        const float* qhirow = qlorow + 8 * QKV_N;
        #pragma unroll
        for (int kk = 0; kk < 8; kk++) {
            float v0 = qlorow[kk * 8 + tig]     * 0.125f;
            float v1 = qhirow[kk * 8 + tig]     * 0.125f;
            float v2 = qlorow[kk * 8 + tig + 4] * 0.125f;
            float v3 = qhirow[kk * 8 + tig + 4] * 0.125f;
            float h0 = __uint_as_float(__float_as_uint(v0) & 0xffffe000u);
            float h1 = __uint_as_float(__float_as_uint(v1) & 0xffffe000u);
            float h2 = __uint_as_float(__float_as_uint(v2) & 0xffffe000u);
            float h3 = __uint_as_float(__float_as_uint(v3) & 0xffffe000u);
            qhi[kk][0] = __float_as_uint(h0);
            qhi[kk][1] = __float_as_uint(h1);
            qhi[kk][2] = __float_as_uint(h2);
            qhi[kk][3] = __float_as_uint(h3);
            qlo[kk][0] = f2tf32(v0 - h0);
            qlo[kk][1] = f2tf32(v1 - h1);
            qlo[kk][2] = f2tf32(v2 - h2);
            qlo[kk][3] = f2tf32(v3 - h3);
        }
    }

    float o[8][4];
    #pragma unroll
    for (int nt = 0; nt < 8; nt++)
        #pragma unroll
        for (int r = 0; r < 4; r++) o[nt][r] = 0.f;
    float m_lo = -1e30f, m_hi = -1e30f;
    float l_lo = 0.f,    l_hi = 0.f;

    uint32_t* Pw = smu + S_P + w * 16 * PSTR;

    for (int kt = 0; kt <= qt; kt++) {
        const int k0 = kt * KT;

        __syncthreads();
        #pragma unroll
        for (int i = 0; i < 8; i++) {
            int idx = i * 128 + tid;
            int r = idx >> 4;
            int c = (idx & 15) * 4;
            const float* krow = base + (size_t)(k0 + r) * QKV_N + EMB + h * HDIM + c;
            float4 kv = *(const float4*)krow;
            float4 vv = *(const float4*)(krow + EMB);
            float kh;
            uint32_t* KH = smu + S_KHI + r * KSTR + c;
            uint32_t* KL = smu + S_KLO + r * KSTR + c;
            kh = __uint_as_float(__float_as_uint(kv.x) & 0xffffe000u); KH[0] = __float_as_uint(kh); KL[0] = f2tf32(kv.x - kh);
            kh = __uint_as_float(__float_as_uint(kv.y) & 0xffffe000u); KH[1] = __float_as_uint(kh); KL[1] = f2tf32(kv.y - kh);
            kh = __uint_as_float(__float_as_uint(kv.z) & 0xffffe000u); KH[2] = __float_as_uint(kh); KL[2] = f2tf32(kv.z - kh);
            kh = __uint_as_float(__float_as_uint(kv.w) & 0xffffe000u); KH[3] = __float_as_uint(kh); KL[3] = f2tf32(kv.w - kh);
            uint32_t* VS = smu + S_V + r * VSTR + c;
            VS[0] = f2tf32(vv.x);
            VS[1] = f2tf32(vv.y);
            VS[2] = f2tf32(vv.z);
            VS[3] = f2tf32(vv.w);
        }
        __syncthreads();

        float s[8][4];
        #pragma unroll
        for (int nt = 0; nt < 8; nt++)
            #pragma unroll
            for (int r = 0; r < 4; r++) s[nt][r] = 0.f;

        #pragma unroll
        for (int kk = 0; kk < 8; kk++) {
            #pragma unroll
            for (int nt = 0; nt < 8; nt++) {
                const int ra = nt * 8 + g;
                uint32_t bh[2], bl[2];
                bh[0] = smu[S_KHI + ra * KSTR + kk * 8 + tig];
                bh[1] = smu[S_KHI + ra * KSTR + kk * 8 + tig + 4];
                bl[0] = smu[S_KLO + ra * KSTR + kk * 8 + tig];
                bl[1] = smu[S_KLO + ra * KSTR + kk * 8 + tig + 4];
                mma_tf32(s[nt], qhi[kk], bh);
                mma_tf32(s[nt], qhi[kk], bl);
                mma_tf32(s[nt], qlo[kk], bh);
            }
        }

        if (kt == qt) {
            const int rlo = w * 16 + g;
            const int rhi = rlo + 8;
            #pragma unroll
            for (int nt = 0; nt < 8; nt++) {
                const int c0 = nt * 8 + 2 * tig;
                if (c0     > rlo) s[nt][0] = -1e30f;
                if (c0 + 1 > rlo) s[nt][1] = -1e30f;
                if (c0     > rhi) s[nt][2] = -1e30f;
                if (c0 + 1 > rhi) s[nt][3] = -1e30f;
            }
        }

        float mx_lo = -1e30f, mx_hi = -1e30f;
        #pragma unroll
        for (int nt = 0; nt < 8; nt++) {
            mx_lo = fmaxf(mx_lo, fmaxf(s[nt][0], s[nt][1]));
            mx_hi = fmaxf(mx_hi, fmaxf(s[nt][2], s[nt][3]));
        }
        mx_lo = fmaxf(mx_lo, __shfl_xor_sync(0xffffffffu, mx_lo, 1));
        mx_lo = fmaxf(mx_lo, __shfl_xor_sync(0xffffffffu, mx_lo, 2));
        mx_hi = fmaxf(mx_hi, __shfl_xor_sync(0xffffffffu, mx_hi, 1));
        mx_hi = fmaxf(mx_hi, __shfl_xor_sync(0xffffffffu, mx_hi, 2));

        const float mn_lo = fmaxf(m_lo, mx_lo);
        const float mn_hi = fmaxf(m_hi, mx_hi);
        const float cr_lo = __expf(m_lo - mn_lo);
        const float cr_hi = __expf(m_hi - mn_hi);
        m_lo = mn_lo; m_hi = mn_hi;
        l_lo *= cr_lo; l_hi *= cr_hi;
        #pragma unroll
        for (int nt = 0; nt < 8; nt++) {
            o[nt][0] *= cr_lo;
            o[nt][1] *= cr_lo;
            o[nt][2] *= cr_hi;
            o[nt][3] *= cr_hi;
        }

        #pragma unroll
        for (int nt = 0; nt < 8; nt++) {
            float p0 = __expf(s[nt][0] - mn_lo);
            float p1 = __expf(s[nt][1] - mn_lo);
            float p2 = __expf(s[nt][2] - mn_hi);
            float p3 = __expf(s[nt][3] - mn_hi);
            l_lo += p0 + p1;
            l_hi += p2 + p3;
            uint32_t* Plo = Pw + g * PSTR + nt * 8 + 2 * tig;
            uint32_t* Phi = Pw + (g + 8) * PSTR + nt * 8 + 2 * tig;
            Plo[0] = f2tf32(p0);
            Plo[1] = f2tf32(p1);
            Phi[0] = f2tf32(p2);
            Phi[1] = f2tf32(p3);
        }
        __syncwarp();

        #pragma unroll
        for (int kk = 0; kk < 8; kk++) {
            uint32_t pa[4];
            pa[0] = Pw[g * PSTR + kk * 8 + tig];
            pa[1] = Pw[(g + 8) * PSTR + kk * 8 + tig];
            pa[2] = Pw[g * PSTR + kk * 8 + tig + 4];
            pa[3] = Pw[(g + 8) * PSTR + kk * 8 + tig + 4];
            #pragma unroll
            for (int nt = 0; nt < 8; nt++) {
                uint32_t vb[2];
                vb[0] = smu[S_V + (kk * 8 + tig) * VSTR + nt * 8 + g];
                vb[1] = smu[S_V + (kk * 8 + tig + 4) * VSTR + nt * 8 + g];
                mma_tf32(o[nt], pa, vb);
            }
        }
        __syncwarp();
    }

    l_lo += __shfl_xor_sync(0xffffffffu, l_lo, 1);
    l_lo += __shfl_xor_sync(0xffffffffu, l_lo, 2);
    l_hi += __shfl_xor_sync(0xffffffffu, l_hi, 1);
    l_hi += __shfl_xor_sync(0xffffffffu, l_hi, 2);
    const float inv_lo = 1.f / l_lo;
    const float inv_hi = 1.f / l_hi;

    const int row_lo = qb + w * 16 + g;
    float* ylo = Y + (size_t)(b * SEQ + row_lo) * EMB + h * HDIM;
    float* yhi = ylo + 8 * EMB;
    #pragma unroll
    for (int nt = 0; nt < 8; nt++) {
        const int col = nt * 8 + 2 * tig;
        float2 v0 = { o[nt][0] * inv_lo, o[nt][1] * inv_lo };
        float2 v1 = { o[nt][2] * inv_hi, o[nt][3] * inv_hi };
        *(float2*)(ylo + col) = v0;
        *(float2*)(yhi + col) = v1;
    }
}

// ===========================================================================
// kernel_launch
// ===========================================================================
extern "C" void kernel_launch(void* const* d_in, const int* in_sizes, int n_in,
                              void* d_out, int out_size)
{
    const float* x      = (const float*)d_in[0];
    const float* W_attn = (const float*)d_in[1];
    const float* b_attn = (const float*)d_in[2];
    const float* W_proj = (const float*)d_in[3];
    const float* b_proj = (const float*)d_in[4];
    float* out = (float*)d_out;

    float *qkv, *y, *wt_attn, *wt_proj;
    cudaGetSymbolAddress((void**)&qkv, g_qkv);
    cudaGetSymbolAddress((void**)&y, g_y);
    cudaGetSymbolAddress((void**)&wt_attn, g_wt_attn);
    cudaGetSymbolAddress((void**)&wt_proj, g_wt_proj);

    static bool attr_set = false;
    if (!attr_set) {
        cudaFuncSetAttribute(flash_mma, cudaFuncAttributeMaxDynamicSharedMemorySize,
                             FLASH_SMEM_BYTES);
        cudaFuncSetAttribute(gemm_mma, cudaFuncAttributeMaxDynamicSharedMemorySize,
                             GEMM_SMEM_BYTES);
        attr_set = true;
    }

    // 0) transpose weights to K-major (N, K), tf32-rounded
    {
        dim3 bdim(32, 8);
        transpose_k<<<dim3(QKV_N / 32, EMB / 32), bdim>>>(W_attn, wt_attn, EMB, QKV_N);
        transpose_k<<<dim3(EMB / 32, EMB / 32), bdim>>>(W_proj, wt_proj, EMB, EMB);
    }

    // 1) QKV projection (mma.sync tf32, cp.async pipeline)
    {
        dim3 grid(QKV_N / BN, M_ROWS / BM);
        gemm_mma<<<grid, 256, GEMM_SMEM_BYTES>>>(x, wt_attn, b_attn, qkv, QKV_N, EMB);
    }

    // 2) causal flash attention (mma.sync tf32, 3xTF32 for QK)
    {
        dim3 grid(SEQ / QT, NHEAD, BATCH);
        flash_mma<<<grid, 128, FLASH_SMEM_BYTES>>>(qkv, y);
    }

    // 3) output projection (mma.sync tf32, cp.async pipeline)
    {
        dim3 grid(EMB / BN, M_ROWS / BM);
        gemm_mma<<<grid, 256, GEMM_SMEM_BYTES>>>(y, wt_proj, b_proj, out, EMB, EMB);
    }
}